// round 5
// baseline (speedup 1.0000x reference)
#include <cuda_runtime.h>

#define NU    100000
#define NI    50000
#define NN    150000        // N_NODES
#define DIM   64
#define VPR   16            // float4 per row
#define F2R   32            // float2 per row
#define E0_   600000
#define E2    (2 * E0_)
#define BB    8192
#define L_W   1e-4f
#define FULL  0xFFFFFFFFu

// ---------------- scratch (device globals start zero-initialized) -----------
__device__ float4 g_h1[NN * VPR];        // 38.4 MB
__device__ float4 g_h2[NN * VPR];        // 38.4 MB
__device__ int2   g_adj2[E2];            // 9.6 MB packed (src*VPR, weight bits)
__device__ int2   g_nod[NN];             // (offset, degree)
__device__ int    g_cnt[NN];             // degree counters (reset each run)
__device__ int    g_cur[NN];             // scatter cursors
__device__ float  g_dinv[NN];
__device__ int    g_total;               // running CSR offset (reset each run)

// ---------------- degree count ----------------------------------------------
__global__ void deg_kernel(const int* __restrict__ eu,
                           const int* __restrict__ ei,
                           float* __restrict__ out)
{
    int e = blockIdx.x * blockDim.x + threadIdx.x;
    if (e == 0) out[0] = 0.f;
    if (e >= E0_) return;
    atomicAdd(&g_cnt[eu[e]], 1);
    atomicAdd(&g_cnt[NU + ei[e]], 1);
}

// ---------------- per-node: dinv, CSR offset via global counter --------------
__global__ void node_kernel()
{
    int i = blockIdx.x * blockDim.x + threadIdx.x;
    if (i >= NN) return;
    int c = g_cnt[i];
    g_dinv[i] = (c > 0) ? rsqrtf((float)c) : 0.f;
    int off = atomicAdd(&g_total, c);      // any order is a valid CSR
    g_nod[i] = make_int2(off, c);
    g_cur[i] = off;
    g_cnt[i] = 0;                          // ready for next replay
}

// ---------------- scatter with fused weights ---------------------------------
__global__ void scatter_kernel(const int* __restrict__ eu,
                               const int* __restrict__ ei)
{
    int e = blockIdx.x * blockDim.x + threadIdx.x;
    if (e >= E0_) return;
    int u = eu[e];
    int v = NU + ei[e];
    float w = g_dinv[u] * g_dinv[v];
    int wi = __float_as_int(w);
    g_adj2[atomicAdd(&g_cur[u], 1)] = make_int2(v * VPR, wi);
    g_adj2[atomicAdd(&g_cur[v], 1)] = make_int2(u * VPR, wi);
}

// ---------------- SpMM: warp/node, half-warp per edge, shuffle-free ----------
// SEL=true: two separate bases (Gu/Gi). SEL=false: unified base (h buffer).
template<bool SEL>
__global__ void __launch_bounds__(256)
spmm_kernel(const float4* __restrict__ baseU,
            const float4* __restrict__ baseI,
            float4* __restrict__ dst)
{
    int gw = (blockIdx.x * blockDim.x + threadIdx.x) >> 5;
    if (gw >= NN) return;
    int lane = threadIdx.x & 31;
    int half = lane >> 4;
    int fl   = lane & 15;

    int2 nd = g_nod[gw];
    int beg = nd.x;
    int d   = nd.y;

    float4 acc = make_float4(0.f, 0.f, 0.f, 0.f);

    #pragma unroll 4
    for (int t = half; t < d; t += 2) {
        int2 a = __ldg(&g_adj2[beg + t]);       // L1-broadcast per half-warp
        const float4* p;
        if (SEL)
            p = (a.x < NU * VPR) ? (baseU + a.x) : (baseI + (a.x - NU * VPR));
        else
            p = baseU + a.x;
        float4 h = __ldg(p + fl);
        float w = __int_as_float(a.y);
        acc.x = fmaf(w, h.x, acc.x);
        acc.y = fmaf(w, h.y, acc.y);
        acc.z = fmaf(w, h.z, acc.z);
        acc.w = fmaf(w, h.w, acc.w);
    }
    acc.x += __shfl_xor_sync(FULL, acc.x, 16);
    acc.y += __shfl_xor_sync(FULL, acc.y, 16);
    acc.z += __shfl_xor_sync(FULL, acc.z, 16);
    acc.w += __shfl_xor_sync(FULL, acc.w, 16);
    if (half == 0)
        dst[(long)gw * VPR + fl] = acc;
}

// ---------------- loss with on-the-fly layer 3 --------------------------------
__device__ __forceinline__ float log_sigmoid(float x)
{
    return fminf(x, 0.f) - log1pf(expf(-fabsf(x)));
}

// emb = 0.25 * (x + h1 + h2 + h3(node)); h3 from h2 via packed CSR
__device__ __forceinline__ float2 emb3(const float2* __restrict__ xrow,
                                       int node, int lane)
{
    const float2* h1 = (const float2*)g_h1;
    const float2* h2 = (const float2*)g_h2;
    long o = (long)node * F2R + lane;
    float2 a = __ldg(xrow + lane);
    float2 b = h1[o];
    float2 c = h2[o];
    float ex = a.x + b.x + c.x;
    float ey = a.y + b.y + c.y;

    int2 nd = g_nod[node];
    int beg = nd.x;
    int d   = nd.y;

    float hx = 0.f, hy = 0.f;
    #pragma unroll 4
    for (int k = 0; k < d; ++k) {
        int2 e = __ldg(&g_adj2[beg + k]);       // warp-uniform address
        float w = __int_as_float(e.y);
        float2 h = __ldg(&h2[2 * (long)e.x + lane]);
        hx = fmaf(w, h.x, hx);
        hy = fmaf(w, h.y, hy);
    }
    return make_float2(0.25f * (ex + hx), 0.25f * (ey + hy));
}

__global__ void __launch_bounds__(256)
loss_kernel(const float2* __restrict__ Gu,
            const float2* __restrict__ Gi,
            const int* __restrict__ user,
            const int* __restrict__ pos,
            const int* __restrict__ neg,
            float* __restrict__ out)
{
    int gid  = blockIdx.x * blockDim.x + threadIdx.x;
    int wrp  = gid >> 5;
    int lane = gid & 31;
    if (gid == 0) g_total = 0;                  // reset for next replay
    if (wrp >= BB) return;

    int u = user[wrp];
    int p = pos[wrp];
    int n = neg[wrp];

    float2 gu = emb3(Gu + (long)u * F2R, u, lane);
    float2 gp = emb3(Gi + (long)p * F2R, NU + p, lane);
    float2 gn = emb3(Gi + (long)n * F2R, NU + n, lane);

    float dp  = gu.x * gp.x + gu.y * gp.y;
    float dn  = gu.x * gn.x + gu.y * gn.y;
    float ssq = gu.x * gu.x + gu.y * gu.y
              + gp.x * gp.x + gp.y * gp.y
              + gn.x * gn.x + gn.y * gn.y;

    #pragma unroll
    for (int o = 16; o > 0; o >>= 1) {
        dp  += __shfl_xor_sync(FULL, dp,  o);
        dn  += __shfl_xor_sync(FULL, dn,  o);
        ssq += __shfl_xor_sync(FULL, ssq, o);
    }

    if (lane == 0) {
        float mf = -log_sigmoid(dp - dn);
        atomicAdd(out, (mf + L_W * 0.5f * ssq) * (1.f / (float)BB));
    }
}

// ---------------- launch -------------------------------------------------------
extern "C" void kernel_launch(void* const* d_in, const int* in_sizes, int n_in,
                              void* d_out, int out_size)
{
    const float* Gu   = (const float*)d_in[0];
    const float* Gi   = (const float*)d_in[1];
    const int* eu     = (const int*)d_in[2];
    const int* ei     = (const int*)d_in[3];
    const int* user   = (const int*)d_in[4];
    const int* pos    = (const int*)d_in[5];
    const int* neg    = (const int*)d_in[6];
    float* out        = (float*)d_out;

    void *p1, *p2;
    cudaGetSymbolAddress(&p1, g_h1);
    cudaGetSymbolAddress(&p2, g_h2);
    float4* H1 = (float4*)p1;
    float4* H2 = (float4*)p2;

    const int T = 256;
    int gE    = (E0_ + T - 1) / T;
    int gN    = (NN + T - 1) / T;
    int gSp   = (NN * 32 + T - 1) / T;
    int gLoss = (BB * 32 + T - 1) / T;

    deg_kernel<<<gE, T>>>(eu, ei, out);
    node_kernel<<<gN, T>>>();
    scatter_kernel<<<gE, T>>>(eu, ei);

    spmm_kernel<true ><<<gSp, T>>>((const float4*)Gu, (const float4*)Gi, H1);
    spmm_kernel<false><<<gSp, T>>>(H1, nullptr, H2);

    loss_kernel<<<gLoss, T>>>((const float2*)Gu, (const float2*)Gi,
                              user, pos, neg, out);
}

// round 6
// speedup vs baseline: 1.3710x; 1.3710x over previous
#include <cuda_runtime.h>
#include <cuda_fp16.h>

#define NU    100000
#define NI    50000
#define NN    150000        // N_NODES
#define DIM   64
#define VPR   16            // float4 per fp32 row
#define U4R   8             // uint4 per fp16 row (64 halves = 128B)
#define H2R   32            // half2 per fp16 row
#define E0_   600000
#define E2    (2 * E0_)
#define BB    8192
#define L_W   1e-4f
#define FULL  0xFFFFFFFFu

// ---------------- scratch (device globals start zero-initialized) -----------
__device__ uint4  g_x [NN * U4R];        // 19.2 MB fp16 [Gu;Gi]
__device__ uint4  g_h1[NN * U4R];        // 19.2 MB fp16 layer-1 output
__device__ uint4  g_h2[NN * U4R];        // 19.2 MB fp16 layer-2 output
__device__ int2   g_adj2[E2];            // 9.6 MB packed (src node, weight bits)
__device__ int2   g_nod[NN];             // (offset, degree)
__device__ int    g_cnt[NN];             // degree counters (reset each run)
__device__ int    g_cur[NN];             // scatter cursors
__device__ float  g_dinv[NN];
__device__ int    g_total;               // running CSR offset (reset each run)

// ---------------- convert [Gu;Gi] -> fp16 ------------------------------------
__global__ void convert_kernel(const float4* __restrict__ Gu,
                               const float4* __restrict__ Gi)
{
    int i = blockIdx.x * blockDim.x + threadIdx.x;
    if (i >= NN * VPR) return;
    float4 v = (i < NU * VPR) ? __ldg(Gu + i) : __ldg(Gi + i - NU * VPR);
    __half2 a = __floats2half2_rn(v.x, v.y);
    __half2 b = __floats2half2_rn(v.z, v.w);
    uint2 pk;
    pk.x = *(unsigned*)&a;
    pk.y = *(unsigned*)&b;
    ((uint2*)g_x)[i] = pk;
}

// ---------------- degree count -----------------------------------------------
__global__ void deg_kernel(const int* __restrict__ eu,
                           const int* __restrict__ ei,
                           float* __restrict__ out)
{
    int e = blockIdx.x * blockDim.x + threadIdx.x;
    if (e == 0) out[0] = 0.f;
    if (e >= E0_) return;
    atomicAdd(&g_cnt[eu[e]], 1);
    atomicAdd(&g_cnt[NU + ei[e]], 1);
}

// ---------------- per-node: dinv, CSR offset via global counter ---------------
__global__ void node_kernel()
{
    int i = blockIdx.x * blockDim.x + threadIdx.x;
    if (i >= NN) return;
    int c = g_cnt[i];
    g_dinv[i] = (c > 0) ? rsqrtf((float)c) : 0.f;
    int off = atomicAdd(&g_total, c);      // any order is a valid CSR
    g_nod[i] = make_int2(off, c);
    g_cur[i] = off;
    g_cnt[i] = 0;                          // ready for next replay
}

// ---------------- scatter with fused weights ----------------------------------
__global__ void scatter_kernel(const int* __restrict__ eu,
                               const int* __restrict__ ei)
{
    int e = blockIdx.x * blockDim.x + threadIdx.x;
    if (e >= E0_) return;
    int u = eu[e];
    int v = NU + ei[e];
    float w = g_dinv[u] * g_dinv[v];
    int wi = __float_as_int(w);
    g_adj2[atomicAdd(&g_cur[u], 1)] = make_int2(v, wi);
    g_adj2[atomicAdd(&g_cur[v], 1)] = make_int2(u, wi);
}

// ---------------- SpMM: warp/node, quarter-warp/edge, fp16 rows ---------------
// Cooperative 32-entry adjacency prefetch keeps gather chain shuffle-fed.
__global__ void __launch_bounds__(256)
spmm_kernel(const uint4* __restrict__ src, uint4* __restrict__ dst)
{
    int gw = (blockIdx.x * blockDim.x + threadIdx.x) >> 5;
    if (gw >= NN) return;
    int lane = threadIdx.x & 31;
    int q  = lane >> 3;          // quarter id: which edge of the group of 4
    int fq = lane & 7;           // uint4 slot within row (8 x 16B = 128B)

    int2 nd = g_nod[gw];
    int beg = nd.x;
    int d   = nd.y;

    float acc[8] = {0.f, 0.f, 0.f, 0.f, 0.f, 0.f, 0.f, 0.f};

    for (int k0 = 0; k0 < d; k0 += 32) {
        int idx = k0 + lane;
        bool vld = (idx < d);
        int2 a = vld ? __ldg(&g_adj2[beg + idx]) : make_int2(0, 0);
        int s  = a.x;
        int wb = a.y;
        int cnt = min(32, d - k0);
        #pragma unroll 4
        for (int t = 0; t < cnt; t += 4) {
            int  j  = t + q;
            bool pv = (j < cnt);
            int  jj = pv ? j : t;
            int sj = __shfl_sync(FULL, s,  jj);
            int wj = __shfl_sync(FULL, wb, jj);
            if (pv) {
                uint4 hv = __ldg(&src[(long)sj * U4R + fq]);
                float w = __int_as_float(wj);
                const __half2* hp = (const __half2*)&hv;
                #pragma unroll
                for (int i = 0; i < 4; ++i) {
                    float2 f = __half22float2(hp[i]);
                    acc[2*i]   = fmaf(w, f.x, acc[2*i]);
                    acc[2*i+1] = fmaf(w, f.y, acc[2*i+1]);
                }
            }
        }
    }
    // fold the 4 quarters (same fq slot lives in lanes fq, 8+fq, 16+fq, 24+fq)
    #pragma unroll
    for (int i = 0; i < 8; ++i) {
        acc[i] += __shfl_xor_sync(FULL, acc[i], 8);
        acc[i] += __shfl_xor_sync(FULL, acc[i], 16);
    }
    if (q == 0) {
        __half2 o0 = __floats2half2_rn(acc[0], acc[1]);
        __half2 o1 = __floats2half2_rn(acc[2], acc[3]);
        __half2 o2 = __floats2half2_rn(acc[4], acc[5]);
        __half2 o3 = __floats2half2_rn(acc[6], acc[7]);
        uint4 pk;
        pk.x = *(unsigned*)&o0;
        pk.y = *(unsigned*)&o1;
        pk.z = *(unsigned*)&o2;
        pk.w = *(unsigned*)&o3;
        dst[(long)gw * U4R + fq] = pk;
    }
}

// ---------------- loss with on-the-fly layer 3 ---------------------------------
__device__ __forceinline__ float log_sigmoid(float x)
{
    return fminf(x, 0.f) - log1pf(expf(-fabsf(x)));
}

// emb = 0.25 * (x + h1 + h2 + h3(node)); h3 from fp16 h2 via packed CSR
__device__ __forceinline__ float2 emb3(int node, int lane)
{
    const __half2* X  = (const __half2*)g_x;
    const __half2* H1 = (const __half2*)g_h1;
    const __half2* H2 = (const __half2*)g_h2;
    long o = (long)node * H2R + lane;
    float2 a = __half22float2(X[o]);
    float2 b = __half22float2(H1[o]);
    float2 c = __half22float2(H2[o]);
    float ex = a.x + b.x + c.x;
    float ey = a.y + b.y + c.y;

    int2 nd = g_nod[node];
    int beg = nd.x;
    int d   = nd.y;

    float hx = 0.f, hy = 0.f;
    #pragma unroll 4
    for (int k = 0; k < d; ++k) {
        int2 e = __ldg(&g_adj2[beg + k]);       // warp-uniform address
        float w = __int_as_float(e.y);
        float2 h = __half22float2(__ldg(&H2[(long)e.x * H2R + lane]));
        hx = fmaf(w, h.x, hx);
        hy = fmaf(w, h.y, hy);
    }
    return make_float2(0.25f * (ex + hx), 0.25f * (ey + hy));
}

__global__ void __launch_bounds__(256)
loss_kernel(const int* __restrict__ user,
            const int* __restrict__ pos,
            const int* __restrict__ neg,
            float* __restrict__ out)
{
    int gid  = blockIdx.x * blockDim.x + threadIdx.x;
    int wrp  = gid >> 5;
    int lane = gid & 31;
    if (gid == 0) g_total = 0;                  // reset for next replay
    if (wrp >= BB) return;

    int u = user[wrp];
    int p = NU + pos[wrp];
    int n = NU + neg[wrp];

    float2 gu = emb3(u, lane);
    float2 gp = emb3(p, lane);
    float2 gn = emb3(n, lane);

    float dp  = gu.x * gp.x + gu.y * gp.y;
    float dn  = gu.x * gn.x + gu.y * gn.y;
    float ssq = gu.x * gu.x + gu.y * gu.y
              + gp.x * gp.x + gp.y * gp.y
              + gn.x * gn.x + gn.y * gn.y;

    #pragma unroll
    for (int o = 16; o > 0; o >>= 1) {
        dp  += __shfl_xor_sync(FULL, dp,  o);
        dn  += __shfl_xor_sync(FULL, dn,  o);
        ssq += __shfl_xor_sync(FULL, ssq, o);
    }

    if (lane == 0) {
        float mf = -log_sigmoid(dp - dn);
        atomicAdd(out, (mf + L_W * 0.5f * ssq) * (1.f / (float)BB));
    }
}

// ---------------- launch ---------------------------------------------------------
extern "C" void kernel_launch(void* const* d_in, const int* in_sizes, int n_in,
                              void* d_out, int out_size)
{
    const float* Gu   = (const float*)d_in[0];
    const float* Gi   = (const float*)d_in[1];
    const int* eu     = (const int*)d_in[2];
    const int* ei     = (const int*)d_in[3];
    const int* user   = (const int*)d_in[4];
    const int* pos    = (const int*)d_in[5];
    const int* neg    = (const int*)d_in[6];
    float* out        = (float*)d_out;

    void *px, *p1, *p2;
    cudaGetSymbolAddress(&px, g_x);
    cudaGetSymbolAddress(&p1, g_h1);
    cudaGetSymbolAddress(&p2, g_h2);
    uint4* X  = (uint4*)px;
    uint4* H1 = (uint4*)p1;
    uint4* H2 = (uint4*)p2;

    const int T = 256;
    int gCvt  = (NN * VPR + T - 1) / T;
    int gE    = (E0_ + T - 1) / T;
    int gN    = (NN + T - 1) / T;
    int gSp   = (NN * 32 + T - 1) / T;
    int gLoss = (BB * 32 + T - 1) / T;

    deg_kernel<<<gE, T>>>(eu, ei, out);
    convert_kernel<<<gCvt, T>>>((const float4*)Gu, (const float4*)Gi);
    node_kernel<<<gN, T>>>();
    scatter_kernel<<<gE, T>>>(eu, ei);

    spmm_kernel<<<gSp, T>>>(X, H1);
    spmm_kernel<<<gSp, T>>>(H1, H2);

    loss_kernel<<<gLoss, T>>>(user, pos, neg, out);
}

// round 7
// speedup vs baseline: 1.4715x; 1.0733x over previous
#include <cuda_runtime.h>
#include <cuda_fp16.h>

#define NU    100000
#define NI    50000
#define NN    150000        // N_NODES
#define DIM   64
#define VPR   16            // float4 per fp32 row
#define U4R   8             // uint4 per fp16 row (64 halves = 128B)
#define H2R   32            // half2 per fp16 row
#define F2R   32            // float2 per fp32 row
#define E0_   600000
#define E2    (2 * E0_)
#define BB    8192
#define L_W   1e-4f
#define FULL  0xFFFFFFFFu

// ---------------- scratch (device globals start zero-initialized) -----------
__device__ uint4  g_x [NN * U4R];        // 19.2 MB fp16 pre-scaled x̂ = dinv*x
__device__ uint4  g_h1[NN * U4R];        // 19.2 MB fp16 ĥ1 = dinv*h1
__device__ uint4  g_h2[NN * U4R];        // 19.2 MB fp16 ĥ2 = dinv*h2
__device__ int    g_adj[E2];             // 4.8 MB adjacency (src node only)
__device__ int2   g_pos[E0_];            // 4.8 MB per-edge slot positions
__device__ int2   g_nod[NN];             // (offset, degree)
__device__ int    g_cnt[NN];             // degree counters (reset each run)
__device__ float  g_dinv[NN];
__device__ int    g_total;               // running CSR offset (reset each run)

// ---------------- degree + per-edge positions --------------------------------
__global__ void deg_kernel(const int* __restrict__ eu,
                           const int* __restrict__ ei,
                           float* __restrict__ out)
{
    int e = blockIdx.x * blockDim.x + threadIdx.x;
    if (e == 0) out[0] = 0.f;
    if (e >= E0_) return;
    int pu = atomicAdd(&g_cnt[eu[e]], 1);
    int pv = atomicAdd(&g_cnt[NU + ei[e]], 1);
    g_pos[e] = make_int2(pu, pv);
}

// ---------------- per-node: dinv, CSR offset via global counter ---------------
__global__ void node_kernel()
{
    int i = blockIdx.x * blockDim.x + threadIdx.x;
    if (i >= NN) return;
    int c = g_cnt[i];
    g_dinv[i] = (c > 0) ? rsqrtf((float)c) : 0.f;
    int off = atomicAdd(&g_total, c);      // any order is a valid CSR
    g_nod[i] = make_int2(off, c);
    g_cnt[i] = 0;                          // ready for next replay
}

// ---------------- convert: x̂ = dinv * [Gu;Gi] -> fp16 ------------------------
__global__ void convert_kernel(const float4* __restrict__ Gu,
                               const float4* __restrict__ Gi)
{
    int i = blockIdx.x * blockDim.x + threadIdx.x;
    if (i >= NN * VPR) return;
    float4 v = (i < NU * VPR) ? __ldg(Gu + i) : __ldg(Gi + i - NU * VPR);
    float s = g_dinv[i >> 4];
    __half2 a = __floats2half2_rn(s * v.x, s * v.y);
    __half2 b = __floats2half2_rn(s * v.z, s * v.w);
    uint2 pk;
    pk.x = *(unsigned*)&a;
    pk.y = *(unsigned*)&b;
    ((uint2*)g_x)[i] = pk;
}

// ---------------- atomic-free scatter -----------------------------------------
__global__ void scatter_kernel(const int* __restrict__ eu,
                               const int* __restrict__ ei)
{
    int e = blockIdx.x * blockDim.x + threadIdx.x;
    if (e >= E0_) return;
    int u = eu[e];
    int v = NU + ei[e];
    int2 p = g_pos[e];
    g_adj[__ldg(&g_nod[u].x) + p.x] = v;
    g_adj[__ldg(&g_nod[v].x) + p.y] = u;
}

// ---------------- SpMM: ĥ' = dinv² · Σ ĥ[s] (weight-free, fp16 accumulate) ----
__global__ void __launch_bounds__(256)
spmm_kernel(const uint4* __restrict__ src, uint4* __restrict__ dst)
{
    int gw = (blockIdx.x * blockDim.x + threadIdx.x) >> 5;
    if (gw >= NN) return;
    int lane = threadIdx.x & 31;
    int q  = lane >> 3;          // which edge of the group of 4
    int fq = lane & 7;           // uint4 slot within row

    int2 nd = g_nod[gw];
    int beg = nd.x;
    int d   = nd.y;

    __half2 acc2[4];
    #pragma unroll
    for (int i = 0; i < 4; ++i) acc2[i] = __floats2half2_rn(0.f, 0.f);

    for (int k0 = 0; k0 < d; k0 += 32) {
        int idx = k0 + lane;
        int s = (idx < d) ? __ldg(&g_adj[beg + idx]) : 0;
        int cnt = min(32, d - k0);
        #pragma unroll 4
        for (int t = 0; t < cnt; t += 4) {
            int  j  = t + q;
            bool pv = (j < cnt);
            int  jj = pv ? j : t;
            int sj = __shfl_sync(FULL, s, jj);
            if (pv) {
                uint4 hv = __ldg(&src[(long)sj * U4R + fq]);
                const __half2* hp = (const __half2*)&hv;
                acc2[0] = __hadd2(acc2[0], hp[0]);
                acc2[1] = __hadd2(acc2[1], hp[1]);
                acc2[2] = __hadd2(acc2[2], hp[2]);
                acc2[3] = __hadd2(acc2[3], hp[3]);
            }
        }
    }
    // fold the 4 quarters (lanes fq, 8+fq, 16+fq, 24+fq share a slot)
    #pragma unroll
    for (int i = 0; i < 4; ++i) {
        unsigned x = *(unsigned*)&acc2[i];
        unsigned y = __shfl_xor_sync(FULL, x, 8);
        acc2[i] = __hadd2(acc2[i], *(__half2*)&y);
        x = *(unsigned*)&acc2[i];
        y = __shfl_xor_sync(FULL, x, 16);
        acc2[i] = __hadd2(acc2[i], *(__half2*)&y);
    }
    if (q == 0) {
        float dv = g_dinv[gw];
        float d2 = dv * dv;
        uint4 pk;
        unsigned* po = (unsigned*)&pk;
        #pragma unroll
        for (int i = 0; i < 4; ++i) {
            float2 f = __half22float2(acc2[i]);
            __half2 o = __floats2half2_rn(d2 * f.x, d2 * f.y);
            po[i] = *(unsigned*)&o;
        }
        dst[(long)gw * U4R + fq] = pk;
    }
}

// ---------------- loss with on-the-fly layer 3 ---------------------------------
__device__ __forceinline__ float log_sigmoid(float x)
{
    return fminf(x, 0.f) - log1pf(expf(-fabsf(x)));
}

// emb = 0.25*( x + sqrt(deg)*(ĥ1+ĥ2) + dinv*Σ ĥ2[s] )
__device__ __forceinline__ float2 emb3(const float2* __restrict__ xrow,
                                       int node, int lane)
{
    const __half2* H1 = (const __half2*)g_h1;
    const __half2* H2 = (const __half2*)g_h2;
    long o = (long)node * H2R + lane;
    float2 a = __ldg(xrow + lane);
    float2 b = __half22float2(H1[o]);
    float2 c = __half22float2(H2[o]);

    int2 nd = g_nod[node];
    int beg = nd.x;
    int d   = nd.y;
    float dv = g_dinv[node];
    float sq = sqrtf((float)d);

    float hx = 0.f, hy = 0.f;
    #pragma unroll 4
    for (int k = 0; k < d; ++k) {
        int s = __ldg(&g_adj[beg + k]);          // warp-uniform address
        float2 h = __half22float2(__ldg(&H2[(long)s * H2R + lane]));
        hx += h.x;
        hy += h.y;
    }
    return make_float2(0.25f * (a.x + sq * (b.x + c.x) + dv * hx),
                       0.25f * (a.y + sq * (b.y + c.y) + dv * hy));
}

__global__ void __launch_bounds__(256)
loss_kernel(const float2* __restrict__ Gu,
            const float2* __restrict__ Gi,
            const int* __restrict__ user,
            const int* __restrict__ pos,
            const int* __restrict__ neg,
            float* __restrict__ out)
{
    int gid  = blockIdx.x * blockDim.x + threadIdx.x;
    int wrp  = gid >> 5;
    int lane = gid & 31;
    if (gid == 0) g_total = 0;                  // reset for next replay
    if (wrp >= BB) return;

    int u = user[wrp];
    int p = pos[wrp];
    int n = neg[wrp];

    float2 gu = emb3(Gu + (long)u * F2R, u, lane);
    float2 gp = emb3(Gi + (long)p * F2R, NU + p, lane);
    float2 gn = emb3(Gi + (long)n * F2R, NU + n, lane);

    float dp  = gu.x * gp.x + gu.y * gp.y;
    float dn  = gu.x * gn.x + gu.y * gn.y;
    float ssq = gu.x * gu.x + gu.y * gu.y
              + gp.x * gp.x + gp.y * gp.y
              + gn.x * gn.x + gn.y * gn.y;

    #pragma unroll
    for (int o = 16; o > 0; o >>= 1) {
        dp  += __shfl_xor_sync(FULL, dp,  o);
        dn  += __shfl_xor_sync(FULL, dn,  o);
        ssq += __shfl_xor_sync(FULL, ssq, o);
    }

    if (lane == 0) {
        float mf = -log_sigmoid(dp - dn);
        atomicAdd(out, (mf + L_W * 0.5f * ssq) * (1.f / (float)BB));
    }
}

// ---------------- launch ---------------------------------------------------------
extern "C" void kernel_launch(void* const* d_in, const int* in_sizes, int n_in,
                              void* d_out, int out_size)
{
    const float* Gu   = (const float*)d_in[0];
    const float* Gi   = (const float*)d_in[1];
    const int* eu     = (const int*)d_in[2];
    const int* ei     = (const int*)d_in[3];
    const int* user   = (const int*)d_in[4];
    const int* pos    = (const int*)d_in[5];
    const int* neg    = (const int*)d_in[6];
    float* out        = (float*)d_out;

    void *px, *p1, *p2;
    cudaGetSymbolAddress(&px, g_x);
    cudaGetSymbolAddress(&p1, g_h1);
    cudaGetSymbolAddress(&p2, g_h2);
    uint4* X  = (uint4*)px;
    uint4* H1 = (uint4*)p1;
    uint4* H2 = (uint4*)p2;

    const int T = 256;
    int gE    = (E0_ + T - 1) / T;
    int gN    = (NN + T - 1) / T;
    int gCvt  = (NN * VPR + T - 1) / T;
    int gSp   = (NN * 32 + T - 1) / T;
    int gLoss = (BB * 32 + T - 1) / T;

    deg_kernel<<<gE, T>>>(eu, ei, out);
    node_kernel<<<gN, T>>>();
    convert_kernel<<<gCvt, T>>>((const float4*)Gu, (const float4*)Gi);
    scatter_kernel<<<gE, T>>>(eu, ei);

    spmm_kernel<<<gSp, T>>>(X, H1);
    spmm_kernel<<<gSp, T>>>(H1, H2);

    loss_kernel<<<gLoss, T>>>((const float2*)Gu, (const float2*)Gi,
                              user, pos, neg, out);
}